// round 12
// baseline (speedup 1.0000x reference)
#include <cuda_runtime.h>
#include <math.h>

// ---------------------------------------------------------------------------
// Persistent 2-layer LSTM, fp32, f32x2-packed FMA, SMEM-resident weights.
// B=256, T=512, H=512, IN=OUT=1, FUT=16.
// 148 CTAs (49 layer0 + 99 layer1), 256 threads each (thread == batch elem).
// One custom grid barrier per timestep (pipelined), 2 per future step.
// ---------------------------------------------------------------------------

#define Bsz   256
#define Tm    512
#define FUTN  16
#define TT    528            // Tm + FUTN
#define Hd    512
#define HB    (Hd * Bsz)     // one h-matrix, [k][b] layout
#define N0    49             // layer0 CTAs
#define N1    99             // layer1 CTAs
#define NBLK  (N0 + N1)      // 148 <= SM count (B300 148 / GB300 152)

// max smem floats: layer1 weights 1024*24 + bias 24 + aux 24  (layer0 smaller)
#define SMEM_FLOATS (1024 * 24 + 128)
#define SMEM_BYTES  (SMEM_FLOATS * 4)

// global state (device globals: allocation-free)
__device__ float    g_h0[2 * HB];   // double-buffered h of layer0, [k][b]
__device__ float    g_h1[2 * HB];   // double-buffered h of layer1, [k][b]
__device__ float    g_xT[Tm * Bsz]; // transposed input x, [t][b]
__device__ unsigned g_count;
__device__ unsigned g_gen;

typedef unsigned long long ull;

__device__ __forceinline__ void ffma2(ull& a, ull w, ull h) {
    asm("fma.rn.f32x2 %0, %1, %2, %0;" : "+l"(a) : "l"(w), "l"(h));
}
__device__ __forceinline__ ull pack2(float x, float y) {
    ull r; asm("mov.b64 %0, {%1, %2};" : "=l"(r) : "f"(x), "f"(y)); return r;
}
__device__ __forceinline__ float2 unpack2(ull v) {
    float2 r; asm("mov.b64 {%0, %1}, %2;" : "=f"(r.x), "=f"(r.y) : "l"(v)); return r;
}
__device__ __forceinline__ float sigf(float x) { return 1.0f / (1.0f + expf(-x)); }

// sense-free generation barrier; target strictly increasing within a launch,
// monotone across graph replays (each launch reads the starting generation).
__device__ __forceinline__ void gsync(unsigned target) {
    __syncthreads();
    if (threadIdx.x == 0) {
        __threadfence();
        if (atomicAdd(&g_count, 1u) == (unsigned)(NBLK - 1)) {
            atomicExch(&g_count, 0u);
            __threadfence();
            atomicExch(&g_gen, target);
        } else {
            volatile unsigned* vg = &g_gen;
            while (*vg != target) { }
            __threadfence();
        }
    }
    __syncthreads();
}

// ---------------- layer 0 step: gates = xv*Wih0 + h0_prev@Whh0^T + b --------
template <int NH>
__device__ __forceinline__ void l0_step(const float* __restrict__ ws,
                                        const float* __restrict__ biasv,
                                        const float* __restrict__ wihv,
                                        const float* __restrict__ hprev,
                                        float* __restrict__ hout,
                                        float xv, float* cst, int u0) {
    constexpr int NC = 4 * NH, NP = NC / 2, NQ = NC / 4;
    const int tid = threadIdx.x;

    ull acc[NP];
    ull xv2 = pack2(xv, xv);
#pragma unroll
    for (int p = 0; p < NP; p++) {
        acc[p] = ((const ull*)biasv)[p];
        ffma2(acc[p], ((const ull*)wihv)[p], xv2);
    }
    const float* hp = hprev + tid;
    const float* wr = ws;
#pragma unroll 4
    for (int k = 0; k < Hd; k++) {
        float hk = __ldcg(hp); hp += Bsz;
        ull h2 = pack2(hk, hk);
#pragma unroll
        for (int q = 0; q < NQ; q++) {
            ulonglong2 wv = *(const ulonglong2*)(wr + 4 * q);   // LDS.128 broadcast
            ffma2(acc[2 * q],     wv.x, h2);
            ffma2(acc[2 * q + 1], wv.y, h2);
        }
        wr += NC;
    }
    float ga[NC];
#pragma unroll
    for (int p = 0; p < NP; p++) { float2 v = unpack2(acc[p]); ga[2*p] = v.x; ga[2*p+1] = v.y; }
#pragma unroll
    for (int j = 0; j < NH; j++) {
        float ig = sigf(ga[j]);
        float fg = sigf(ga[NH + j]);
        float gg = tanhf(ga[2 * NH + j]);
        float og = sigf(ga[3 * NH + j]);
        float c  = fg * cst[j] + ig * gg;
        cst[j] = c;
        float h = og * tanhf(c);
        __stcg(hout + (u0 + j) * Bsz + tid, h);
    }
}

// ------- layer 1 step: gates = h0@Wih1^T + h1_prev@Whh1^T + b; out dot ------
template <int NH>
__device__ __forceinline__ void l1_step(const float* __restrict__ ws,
                                        const float* __restrict__ biasv,
                                        const float* __restrict__ wlinv,
                                        const float* __restrict__ h0cur,
                                        const float* __restrict__ h1prev,
                                        float* __restrict__ hout,
                                        float* __restrict__ out, int t,
                                        float* cst, int u0) {
    constexpr int NC = 4 * NH, NP = NC / 2, NQ = NC / 4;
    const int tid = threadIdx.x;

    ull acc[NP];
#pragma unroll
    for (int p = 0; p < NP; p++) acc[p] = ((const ull*)biasv)[p];

    const float* wr = ws;
    const float* hp = h0cur + tid;
#pragma unroll 4
    for (int k = 0; k < Hd; k++) {
        float hk = __ldcg(hp); hp += Bsz;
        ull h2 = pack2(hk, hk);
#pragma unroll
        for (int q = 0; q < NQ; q++) {
            ulonglong2 wv = *(const ulonglong2*)(wr + 4 * q);
            ffma2(acc[2 * q],     wv.x, h2);
            ffma2(acc[2 * q + 1], wv.y, h2);
        }
        wr += NC;
    }
    hp = h1prev + tid;
#pragma unroll 4
    for (int k = 0; k < Hd; k++) {
        float hk = __ldcg(hp); hp += Bsz;
        ull h2 = pack2(hk, hk);
#pragma unroll
        for (int q = 0; q < NQ; q++) {
            ulonglong2 wv = *(const ulonglong2*)(wr + 4 * q);
            ffma2(acc[2 * q],     wv.x, h2);
            ffma2(acc[2 * q + 1], wv.y, h2);
        }
        wr += NC;
    }
    float ga[NC];
#pragma unroll
    for (int p = 0; p < NP; p++) { float2 v = unpack2(acc[p]); ga[2*p] = v.x; ga[2*p+1] = v.y; }
    float outp = 0.0f;
#pragma unroll
    for (int j = 0; j < NH; j++) {
        float ig = sigf(ga[j]);
        float fg = sigf(ga[NH + j]);
        float gg = tanhf(ga[2 * NH + j]);
        float og = sigf(ga[3 * NH + j]);
        float c  = fg * cst[j] + ig * gg;
        cst[j] = c;
        float h = og * tanhf(c);
        outp += wlinv[j] * h;
        __stcg(hout + (u0 + j) * Bsz + tid, h);
    }
    atomicAdd(out + tid * TT + t, outp);   // 99-way partial reduction of Wlin dot
}

// ---------------- per-CTA main loops (barrier sequence identical) -----------
template <int NH>
__device__ __noinline__ void run_l0(const float* ws, const float* biasv, const float* wihv,
                                    float* out, int u0, unsigned gen0) {
    const int tid = threadIdx.x;
    float cst[NH];
#pragma unroll
    for (int j = 0; j < NH; j++) cst[j] = 0.0f;
    unsigned nbar = 2;
    // pipelined main phase: interval s computes layer0 of timestep s
    for (int s = 0; s <= Tm; s++) {
        if (s < Tm) {
            float xv = g_xT[s * Bsz + tid];
            l0_step<NH>(ws, biasv, wihv,
                        g_h0 + ((unsigned)(s + 1) & 1u) * HB,   // h0(s-1)
                        g_h0 + ((unsigned)s & 1u) * HB,         // h0(s)
                        xv, cst, u0);
        }
        gsync(gen0 + nbar); nbar++;
    }
    // future phase: 2-stage (layer0 needs out[t-1], produced by layer1 at t-1)
    for (int f = 0; f < FUTN; f++) {
        int t = Tm + f;
        float xv = __ldcg(&out[tid * TT + (t - 1)]);
        l0_step<NH>(ws, biasv, wihv,
                    g_h0 + ((unsigned)(t + 1) & 1u) * HB,
                    g_h0 + ((unsigned)t & 1u) * HB,
                    xv, cst, u0);
        gsync(gen0 + nbar); nbar++;   // stage A barrier
        gsync(gen0 + nbar); nbar++;   // stage B barrier (layer1 working)
    }
}

template <int NH>
__device__ __noinline__ void run_l1(const float* ws, const float* biasv, const float* wlinv,
                                    float* out, int u0, unsigned gen0) {
    float cst[NH];
#pragma unroll
    for (int j = 0; j < NH; j++) cst[j] = 0.0f;
    unsigned nbar = 2;
    // pipelined main phase: interval s computes layer1 of timestep s-1
    for (int s = 0; s <= Tm; s++) {
        if (s >= 1) {
            int t = s - 1;
            l1_step<NH>(ws, biasv, wlinv,
                        g_h0 + ((unsigned)t & 1u) * HB,          // h0(t)
                        g_h1 + ((unsigned)(t + 1) & 1u) * HB,    // h1(t-1)
                        g_h1 + ((unsigned)t & 1u) * HB,          // h1(t)
                        out, t, cst, u0);
        }
        gsync(gen0 + nbar); nbar++;
    }
    for (int f = 0; f < FUTN; f++) {
        int t = Tm + f;
        gsync(gen0 + nbar); nbar++;   // stage A barrier (layer0 working)
        l1_step<NH>(ws, biasv, wlinv,
                    g_h0 + ((unsigned)t & 1u) * HB,
                    g_h1 + ((unsigned)(t + 1) & 1u) * HB,
                    g_h1 + ((unsigned)t & 1u) * HB,
                    out, t, cst, u0);
        gsync(gen0 + nbar); nbar++;   // stage B barrier
    }
}

// ---------------------------------------------------------------------------
__global__ void __launch_bounds__(256, 1)
lstm_persistent_kernel(const float* __restrict__ x,
                       const float* __restrict__ Wih0, const float* __restrict__ Whh0,
                       const float* __restrict__ bih0, const float* __restrict__ bhh0,
                       const float* __restrict__ Wih1, const float* __restrict__ Whh1,
                       const float* __restrict__ bih1, const float* __restrict__ bhh1,
                       const float* __restrict__ Wlin, const float* __restrict__ blin,
                       float* __restrict__ out) {
    extern __shared__ float smem[];
    const int tid = threadIdx.x;
    const int bid = blockIdx.x;

    __shared__ unsigned s_gen0;
    if (tid == 0) s_gen0 = *((volatile unsigned*)&g_gen);
    __syncthreads();
    const unsigned gen0 = s_gen0;

    const bool isL0 = (bid < N0);
    const int  gi   = isL0 ? bid : bid - N0;
    int u0, u1;
    if (isL0) { u0 = (Hd * gi) / N0; u1 = (Hd * (gi + 1)) / N0; }
    else      { u0 = (Hd * gi) / N1; u1 = (Hd * (gi + 1)) / N1; }
    const int nh = u1 - u0;
    const int nc = 4 * nh;
    const int K  = isL0 ? Hd : 2 * Hd;

    float* ws    = smem;            // [K][nc]  (k-major so 4 adjacent cols = LDS.128)
    float* biasv = smem + K * nc;   // [nc]  bih+bhh, gate-major
    float* auxv  = biasv + nc;      // layer0: Wih0 col [nc]; layer1: Wlin [nh]

    // ---- one-time weight staging into SMEM --------------------------------
    if (isL0) {
        for (int c = 0; c < nc; c++) {
            int g = c / nh, j = c - g * nh;
            int row = g * Hd + u0 + j;
            for (int k = tid; k < Hd; k += 256) ws[k * nc + c] = Whh0[row * Hd + k];
            if (tid == 0) { biasv[c] = bih0[row] + bhh0[row]; auxv[c] = Wih0[row]; }
        }
    } else {
        for (int c = 0; c < nc; c++) {
            int g = c / nh, j = c - g * nh;
            int row = g * Hd + u0 + j;
            for (int k = tid; k < Hd; k += 256) {
                ws[k * nc + c]        = Wih1[row * Hd + k];
                ws[(Hd + k) * nc + c] = Whh1[row * Hd + k];
            }
            if (tid == 0) biasv[c] = bih1[row] + bhh1[row];
        }
        if (tid == 0) for (int j = 0; j < nh; j++) auxv[j] = Wlin[u0 + j];
    }

    // ---- per-launch global state init (idempotent across graph replays) ---
    const float bl = blin[0];
    for (int i = bid * 256 + tid; i < Bsz * TT; i += NBLK * 256) __stcg(&out[i], bl);
    for (int i = bid * 256 + tid; i < 2 * HB; i += NBLK * 256) {
        __stcg(&g_h0[i], 0.0f);
        __stcg(&g_h1[i], 0.0f);
    }
    for (int i = bid * 256 + tid; i < Bsz * Tm; i += NBLK * 256) {
        int b = i / Tm, t = i - b * Tm;
        __stcg(&g_xT[t * Bsz + b], x[i]);          // transpose x -> [t][b]
    }
    gsync(gen0 + 1);

    if (isL0) {
        if (nh == 11) run_l0<11>(ws, biasv, auxv, out, u0, gen0);
        else          run_l0<10>(ws, biasv, auxv, out, u0, gen0);
    } else {
        if (nh == 6)  run_l1<6 >(ws, biasv, auxv, out, u0, gen0);
        else          run_l1<5 >(ws, biasv, auxv, out, u0, gen0);
    }
}

// ---------------------------------------------------------------------------
extern "C" void kernel_launch(void* const* d_in, const int* in_sizes, int n_in,
                              void* d_out, int out_size) {
    (void)in_sizes; (void)n_in; (void)out_size;
    const float* x    = (const float*)d_in[0];
    const float* Wih0 = (const float*)d_in[1];
    const float* Whh0 = (const float*)d_in[2];
    const float* bih0 = (const float*)d_in[3];
    const float* bhh0 = (const float*)d_in[4];
    const float* Wih1 = (const float*)d_in[5];
    const float* Whh1 = (const float*)d_in[6];
    const float* bih1 = (const float*)d_in[7];
    const float* bhh1 = (const float*)d_in[8];
    const float* Wlin = (const float*)d_in[9];
    const float* blin = (const float*)d_in[10];
    float* out = (float*)d_out;

    cudaFuncSetAttribute(lstm_persistent_kernel,
                         cudaFuncAttributeMaxDynamicSharedMemorySize, SMEM_BYTES);

    lstm_persistent_kernel<<<NBLK, 256, SMEM_BYTES>>>(
        x, Wih0, Whh0, bih0, bhh0, Wih1, Whh1, bih1, bhh1, Wlin, blin, out);
}

// round 14
// speedup vs baseline: 1.3539x; 1.3539x over previous
#include <cuda_runtime.h>
#include <math.h>

// ---------------------------------------------------------------------------
// Persistent 2-layer LSTM, fp32, f32x2 FMA, SMEM weights.
// R12: batch-pair threads + 2 column groups -> LDS:FMA ratio 1:4 (was 1:2),
//      8-deep explicit h prefetch. 148 CTAs x 256 threads.
// ---------------------------------------------------------------------------

#define Bsz   256
#define Tm    512
#define FUTN  16
#define TT    528
#define Hd    512
#define HB    (Hd * Bsz)
#define N0    49
#define N1    99
#define NBLK  (N0 + N1)

#define SMEM_BYTES (36000 * 4)   // max: layer0 nh=11 -> 35928 floats

__device__ float    g_h0[2 * HB];
__device__ float    g_h1[2 * HB];
__device__ float    g_xT[Tm * Bsz];
__device__ unsigned g_count;
__device__ unsigned g_gen;

typedef unsigned long long ull;

__device__ __forceinline__ void ffma2(ull& a, ull w, ull h) {
    asm("fma.rn.f32x2 %0, %1, %2, %0;" : "+l"(a) : "l"(w), "l"(h));
}
__device__ __forceinline__ ull pack2(float x, float y) {
    ull r; asm("mov.b64 %0, {%1, %2};" : "=l"(r) : "f"(x), "f"(y)); return r;
}
__device__ __forceinline__ float sigf(float x) { return 1.0f / (1.0f + expf(-x)); }

// grid barrier: generation target strictly increasing, monotone across replays
__device__ __forceinline__ void gsync(unsigned target) {
    __syncthreads();
    if (threadIdx.x == 0) {
        __threadfence();
        if (atomicAdd(&g_count, 1u) == (unsigned)(NBLK - 1)) {
            atomicExch(&g_count, 0u);
            __threadfence();
            atomicExch(&g_gen, target);
        } else {
            volatile unsigned* vg = &g_gen;
            while (*vg != target) { }
            __threadfence();
        }
    }
    __syncthreads();
}

// ---- K=512 dot: acc(col-pair)(batch0/1) += W[k][cols] * h[k][b] ------------
template <int NCH, int RS>
__device__ __forceinline__ void dotloop512(ull* accA, ull* accB,
                                           const float* __restrict__ wsg,
                                           const float2* __restrict__ hp) {
    constexpr int NQ = NCH / 4, REM = NCH % 4, NCP = NCH / 2;
    constexpr int U = 8;
    float2 hbuf[U];
#pragma unroll
    for (int uu = 0; uu < U; uu++) hbuf[uu] = __ldcg(hp + uu * (Bsz / 2));
    const float* wr = wsg;
#pragma unroll 1
    for (int k0 = 0; k0 < Hd; k0 += U) {
        float2 hn[U];
        if (k0 + U < Hd) {
#pragma unroll
            for (int uu = 0; uu < U; uu++)
                hn[uu] = __ldcg(hp + (k0 + U + uu) * (Bsz / 2));
        }
#pragma unroll
        for (int uu = 0; uu < U; uu++) {
            ull hA = pack2(hbuf[uu].x, hbuf[uu].x);
            ull hB = pack2(hbuf[uu].y, hbuf[uu].y);
#pragma unroll
            for (int q = 0; q < NQ; q++) {
                ulonglong2 wv = *(const ulonglong2*)(wr + 4 * q);  // LDS.128 bcast
                ffma2(accA[2 * q],     wv.x, hA);
                ffma2(accB[2 * q],     wv.x, hB);
                ffma2(accA[2 * q + 1], wv.y, hA);
                ffma2(accB[2 * q + 1], wv.y, hB);
            }
            if (REM) {
                ull wv = *(const ull*)(wr + 4 * NQ);
                ffma2(accA[NCP - 1], wv, hA);
                ffma2(accB[NCP - 1], wv, hB);
            }
            wr += RS;
        }
#pragma unroll
        for (int uu = 0; uu < U; uu++) hbuf[uu] = hn[uu];
    }
}

// ---------------- layer 0 step ----------------------------------------------
template <int NH>
__device__ __forceinline__ void l0_step(const float* __restrict__ ws,
                                        const float* __restrict__ biasv,
                                        const float* __restrict__ wihv,
                                        float* __restrict__ gbuf,
                                        const float* __restrict__ hprev,
                                        float* __restrict__ hout,
                                        float2 xv, float* cst,
                                        int u0, int half, int l) {
    constexpr int NC = 4 * NH, NCH = 2 * NH, GP = (NCH + 3) & ~3, RS = 2 * GP;
    constexpr int NCP = NCH / 2;
    const int b0 = 2 * l;
    ull accA[NCP], accB[NCP];
    const ull* bh  = (const ull*)(biasv + half * NCH);
    const ull* wih = (const ull*)(wihv + half * NCH);
    ull xA = pack2(xv.x, xv.x), xB = pack2(xv.y, xv.y);
#pragma unroll
    for (int p = 0; p < NCP; p++) {
        ull b = bh[p];
        accA[p] = b; accB[p] = b;
        ull w = wih[p];
        ffma2(accA[p], w, xA);
        ffma2(accB[p], w, xB);
    }
    dotloop512<NCH, RS>(accA, accB, ws + half * GP, (const float2*)(hprev + b0));
    // exchange gate pre-activations via SMEM (group0: i,f ; group1: g,o)
    float* gAo = gbuf + b0 * NC + half * NCH;
    float* gBo = gbuf + (b0 + 1) * NC + half * NCH;
#pragma unroll
    for (int p = 0; p < NCP; p++) { ((ull*)gAo)[p] = accA[p]; ((ull*)gBo)[p] = accB[p]; }
    __syncthreads();
    constexpr int NU0 = (NH + 1) / 2;
    const int uoff = half ? NU0 : 0;
    const int nup  = half ? (NH - NU0) : NU0;
    const float* gA = gbuf + b0 * NC;
    const float* gB = gbuf + (b0 + 1) * NC;
#pragma unroll
    for (int jj = 0; jj < NU0; jj++) {
        if (jj < nup) {
            int j = uoff + jj;
            float iA = sigf(gA[j]),          iB = sigf(gB[j]);
            float fA = sigf(gA[NH + j]),     fB = sigf(gB[NH + j]);
            float gg = tanhf(gA[2 * NH + j]), gh = tanhf(gB[2 * NH + j]);
            float oA = sigf(gA[3 * NH + j]), oB = sigf(gB[3 * NH + j]);
            float cA = fA * cst[2 * jj]     + iA * gg;
            float cB = fB * cst[2 * jj + 1] + iB * gh;
            cst[2 * jj] = cA; cst[2 * jj + 1] = cB;
            float2 hv = make_float2(oA * tanhf(cA), oB * tanhf(cB));
            __stcg((float2*)&hout[(u0 + j) * Bsz + b0], hv);
        }
    }
}

// ---------------- layer 1 step ----------------------------------------------
template <int NH>
__device__ __forceinline__ void l1_step(const float* __restrict__ ws,
                                        const float* __restrict__ biasv,
                                        const float* __restrict__ wlinv,
                                        float* __restrict__ gbuf,
                                        const float* __restrict__ h0cur,
                                        const float* __restrict__ h1prev,
                                        float* __restrict__ hout,
                                        float* __restrict__ out, int t,
                                        float* cst, int u0, int half, int l) {
    constexpr int NC = 4 * NH, NCH = 2 * NH, GP = (NCH + 3) & ~3, RS = 2 * GP;
    constexpr int NCP = NCH / 2;
    const int b0 = 2 * l;
    ull accA[NCP], accB[NCP];
    const ull* bh = (const ull*)(biasv + half * NCH);
#pragma unroll
    for (int p = 0; p < NCP; p++) { accA[p] = bh[p]; accB[p] = bh[p]; }
    dotloop512<NCH, RS>(accA, accB, ws + half * GP,            (const float2*)(h0cur  + b0));
    dotloop512<NCH, RS>(accA, accB, ws + Hd * RS + half * GP,  (const float2*)(h1prev + b0));
    float* gAo = gbuf + b0 * NC + half * NCH;
    float* gBo = gbuf + (b0 + 1) * NC + half * NCH;
#pragma unroll
    for (int p = 0; p < NCP; p++) { ((ull*)gAo)[p] = accA[p]; ((ull*)gBo)[p] = accB[p]; }
    __syncthreads();
    constexpr int NU0 = (NH + 1) / 2;
    const int uoff = half ? NU0 : 0;
    const int nup  = half ? (NH - NU0) : NU0;
    const float* gA = gbuf + b0 * NC;
    const float* gB = gbuf + (b0 + 1) * NC;
    float sA = 0.0f, sB = 0.0f;
#pragma unroll
    for (int jj = 0; jj < NU0; jj++) {
        if (jj < nup) {
            int j = uoff + jj;
            float iA = sigf(gA[j]),          iB = sigf(gB[j]);
            float fA = sigf(gA[NH + j]),     fB = sigf(gB[NH + j]);
            float gg = tanhf(gA[2 * NH + j]), gh = tanhf(gB[2 * NH + j]);
            float oA = sigf(gA[3 * NH + j]), oB = sigf(gB[3 * NH + j]);
            float cA = fA * cst[2 * jj]     + iA * gg;
            float cB = fB * cst[2 * jj + 1] + iB * gh;
            cst[2 * jj] = cA; cst[2 * jj + 1] = cB;
            float hA_ = oA * tanhf(cA), hB_ = oB * tanhf(cB);
            sA += wlinv[j] * hA_;  sB += wlinv[j] * hB_;
            __stcg((float2*)&hout[(u0 + j) * Bsz + b0], make_float2(hA_, hB_));
        }
    }
    atomicAdd(out + b0 * TT + t, sA);
    atomicAdd(out + (b0 + 1) * TT + t, sB);
}

// ---------------- per-CTA loops (barrier sequences identical) ---------------
template <int NH>
__device__ __noinline__ void run_l0(const float* ws, const float* biasv, const float* wihv,
                                    float* gbuf, float* out, int u0, unsigned gen0,
                                    int half, int l) {
    constexpr int NU0 = (NH + 1) / 2;
    float cst[2 * NU0];
#pragma unroll
    for (int j = 0; j < 2 * NU0; j++) cst[j] = 0.0f;
    const int b0 = 2 * l;
    unsigned nbar = 2;
    for (int s = 0; s <= Tm; s++) {
        if (s < Tm) {
            float2 xv = *(const float2*)&g_xT[s * Bsz + b0];
            l0_step<NH>(ws, biasv, wihv, gbuf,
                        g_h0 + ((unsigned)(s + 1) & 1u) * HB,
                        g_h0 + ((unsigned)s & 1u) * HB,
                        xv, cst, u0, half, l);
        }
        gsync(gen0 + nbar); nbar++;
    }
    for (int f = 0; f < FUTN; f++) {
        int t = Tm + f;
        float2 xv;
        xv.x = __ldcg(&out[b0 * TT + (t - 1)]);
        xv.y = __ldcg(&out[(b0 + 1) * TT + (t - 1)]);
        l0_step<NH>(ws, biasv, wihv, gbuf,
                    g_h0 + ((unsigned)(t + 1) & 1u) * HB,
                    g_h0 + ((unsigned)t & 1u) * HB,
                    xv, cst, u0, half, l);
        gsync(gen0 + nbar); nbar++;
        gsync(gen0 + nbar); nbar++;
    }
}

template <int NH>
__device__ __noinline__ void run_l1(const float* ws, const float* biasv, const float* wlinv,
                                    float* gbuf, float* out, int u0, unsigned gen0,
                                    int half, int l) {
    constexpr int NU0 = (NH + 1) / 2;
    float cst[2 * NU0];
#pragma unroll
    for (int j = 0; j < 2 * NU0; j++) cst[j] = 0.0f;
    unsigned nbar = 2;
    for (int s = 0; s <= Tm; s++) {
        if (s >= 1) {
            int t = s - 1;
            l1_step<NH>(ws, biasv, wlinv, gbuf,
                        g_h0 + ((unsigned)t & 1u) * HB,
                        g_h1 + ((unsigned)(t + 1) & 1u) * HB,
                        g_h1 + ((unsigned)t & 1u) * HB,
                        out, t, cst, u0, half, l);
        }
        gsync(gen0 + nbar); nbar++;
    }
    for (int f = 0; f < FUTN; f++) {
        int t = Tm + f;
        gsync(gen0 + nbar); nbar++;
        l1_step<NH>(ws, biasv, wlinv, gbuf,
                    g_h0 + ((unsigned)t & 1u) * HB,
                    g_h1 + ((unsigned)(t + 1) & 1u) * HB,
                    g_h1 + ((unsigned)t & 1u) * HB,
                    out, t, cst, u0, half, l);
        gsync(gen0 + nbar); nbar++;
    }
}

// ---------------------------------------------------------------------------
__global__ void __launch_bounds__(256, 1)
lstm_persistent_kernel(const float* __restrict__ x,
                       const float* __restrict__ Wih0, const float* __restrict__ Whh0,
                       const float* __restrict__ bih0, const float* __restrict__ bhh0,
                       const float* __restrict__ Wih1, const float* __restrict__ Whh1,
                       const float* __restrict__ bih1, const float* __restrict__ bhh1,
                       const float* __restrict__ Wlin, const float* __restrict__ blin,
                       float* __restrict__ out) {
    extern __shared__ float smem[];
    const int tid = threadIdx.x;
    const int bid = blockIdx.x;
    const int half = tid >> 7;
    const int l    = tid & 127;

    __shared__ unsigned s_gen0;
    if (tid == 0) s_gen0 = *((volatile unsigned*)&g_gen);
    __syncthreads();
    const unsigned gen0 = s_gen0;

    const bool isL0 = (bid < N0);
    const int  gi   = isL0 ? bid : bid - N0;
    int u0, u1;
    if (isL0) { u0 = (Hd * gi) / N0; u1 = (Hd * (gi + 1)) / N0; }
    else      { u0 = (Hd * gi) / N1; u1 = (Hd * (gi + 1)) / N1; }
    const int nh  = u1 - u0;
    const int nc  = 4 * nh;
    const int nch = 2 * nh;
    const int gp  = (nch + 3) & ~3;
    const int rs  = 2 * gp;
    const int K   = isL0 ? Hd : 2 * Hd;

    float* ws    = smem;            // [K][rs] padded, group g at col offset g*gp
    float* biasv = smem + K * rs;   // [nc] gate-major (bih+bhh)
    float* auxv  = biasv + nc;      // layer0: Wih0 col [nc]; layer1: Wlin [nh]
    float* gbuf  = auxv + nc;       // [Bsz][nc] gate exchange

    // ---- one-time weight staging ------------------------------------------
    if (isL0) {
        for (int c = 0; c < nc; c++) {
            int g = c / nch, lc = c - g * nch;
            int gate = c / nh, j = c - gate * nh;
            int row = gate * Hd + u0 + j;
            int dc = g * gp + lc;
            for (int k = tid; k < Hd; k += 256) ws[k * rs + dc] = Whh0[row * Hd + k];
            if (tid == 0) { biasv[c] = bih0[row] + bhh0[row]; auxv[c] = Wih0[row]; }
        }
    } else {
        for (int c = 0; c < nc; c++) {
            int g = c / nch, lc = c - g * nch;
            int gate = c / nh, j = c - gate * nh;
            int row = gate * Hd + u0 + j;
            int dc = g * gp + lc;
            for (int k = tid; k < Hd; k += 256) {
                ws[k * rs + dc]        = Wih1[row * Hd + k];
                ws[(Hd + k) * rs + dc] = Whh1[row * Hd + k];
            }
            if (tid == 0) biasv[c] = bih1[row] + bhh1[row];
        }
        if (tid == 0) for (int j = 0; j < nh; j++) auxv[j] = Wlin[u0 + j];
    }

    // ---- per-launch global init (idempotent across graph replays) ---------
    const float bl = blin[0];
    for (int i = bid * 256 + tid; i < Bsz * TT; i += NBLK * 256) __stcg(&out[i], bl);
    for (int i = bid * 256 + tid; i < 2 * HB; i += NBLK * 256) {
        __stcg(&g_h0[i], 0.0f);
        __stcg(&g_h1[i], 0.0f);
    }
    for (int i = bid * 256 + tid; i < Bsz * Tm; i += NBLK * 256) {
        int b = i / Tm, t = i - b * Tm;
        __stcg(&g_xT[t * Bsz + b], x[i]);
    }
    gsync(gen0 + 1);

    if (isL0) {
        if (nh == 11) run_l0<11>(ws, biasv, auxv, gbuf, out, u0, gen0, half, l);
        else          run_l0<10>(ws, biasv, auxv, gbuf, out, u0, gen0, half, l);
    } else {
        if (nh == 6)  run_l1<6 >(ws, biasv, auxv, gbuf, out, u0, gen0, half, l);
        else          run_l1<5 >(ws, biasv, auxv, gbuf, out, u0, gen0, half, l);
    }
}

// ---------------------------------------------------------------------------
extern "C" void kernel_launch(void* const* d_in, const int* in_sizes, int n_in,
                              void* d_out, int out_size) {
    (void)in_sizes; (void)n_in; (void)out_size;
    const float* x    = (const float*)d_in[0];
    const float* Wih0 = (const float*)d_in[1];
    const float* Whh0 = (const float*)d_in[2];
    const float* bih0 = (const float*)d_in[3];
    const float* bhh0 = (const float*)d_in[4];
    const float* Wih1 = (const float*)d_in[5];
    const float* Whh1 = (const float*)d_in[6];
    const float* bih1 = (const float*)d_in[7];
    const float* bhh1 = (const float*)d_in[8];
    const float* Wlin = (const float*)d_in[9];
    const float* blin = (const float*)d_in[10];
    float* out = (float*)d_out;

    cudaFuncSetAttribute(lstm_persistent_kernel,
                         cudaFuncAttributeMaxDynamicSharedMemorySize, SMEM_BYTES);

    lstm_persistent_kernel<<<NBLK, 256, SMEM_BYTES>>>(
        x, Wih0, Whh0, bih0, bhh0, Wih1, Whh1, bih1, bhh1, Wlin, blin, out);
}

// round 16
// speedup vs baseline: 1.4464x; 1.0684x over previous
#include <cuda_runtime.h>
#include <math.h>

// ---------------------------------------------------------------------------
// Persistent 2-layer LSTM, fp32, f32x2 FMA, SMEM weights.
// R14: 512 threads/CTA = (2 column-halves) x (2 K-halves) x 128 batch-pair
//      threads -> 4 warps/SMSP for latency hiding, same FMA/LDS floors.
// ---------------------------------------------------------------------------

#define Bsz   256
#define Tm    512
#define FUTN  16
#define TT    528
#define Hd    512
#define HB    (Hd * Bsz)
#define N0    49
#define N1    99
#define NBLK  (N0 + N1)
#define NTHR  512

#define SMEM_BYTES (36000 * 4)   // max: layer0 nh=11 -> 35928 floats

__device__ float    g_h0[2 * HB];
__device__ float    g_h1[2 * HB];
__device__ float    g_xT[Tm * Bsz];
__device__ unsigned g_count;
__device__ unsigned g_gen;

typedef unsigned long long ull;

__device__ __forceinline__ void ffma2(ull& a, ull w, ull h) {
    asm("fma.rn.f32x2 %0, %1, %2, %0;" : "+l"(a) : "l"(w), "l"(h));
}
__device__ __forceinline__ ull pack2(float x, float y) {
    ull r; asm("mov.b64 %0, {%1, %2};" : "=l"(r) : "f"(x), "f"(y)); return r;
}
__device__ __forceinline__ float2 unpack2(ull v) {
    float2 r; asm("mov.b64 {%0, %1}, %2;" : "=f"(r.x), "=f"(r.y) : "l"(v)); return r;
}
__device__ __forceinline__ float sigf(float x) { return 1.0f / (1.0f + expf(-x)); }

// grid barrier: generation target strictly increasing, monotone across replays
__device__ __forceinline__ void gsync(unsigned target) {
    __syncthreads();
    if (threadIdx.x == 0) {
        __threadfence();
        if (atomicAdd(&g_count, 1u) == (unsigned)(NBLK - 1)) {
            atomicExch(&g_count, 0u);
            __threadfence();
            atomicExch(&g_gen, target);
        } else {
            volatile unsigned* vg = &g_gen;
            while (*vg != target) { }
            __threadfence();
        }
    }
    __syncthreads();
}

// ---- K-chunk dot: acc(col-pair)(batch0/1) += W[k][cols] * h[k][b] ----------
template <int NCH, int RS, int KLEN>
__device__ __forceinline__ void dotloop(ull* accA, ull* accB,
                                        const float* wr,
                                        const float2* __restrict__ hp) {
    constexpr int NQ = NCH / 4, REM = NCH % 4, NCP = NCH / 2;
    constexpr int U = 4;
    float2 hbuf[U];
#pragma unroll
    for (int uu = 0; uu < U; uu++) hbuf[uu] = __ldcg(hp + uu * (Bsz / 2));
#pragma unroll 1
    for (int k0 = 0; k0 < KLEN; k0 += U) {
        float2 hn[U];
        if (k0 + U < KLEN) {
#pragma unroll
            for (int uu = 0; uu < U; uu++)
                hn[uu] = __ldcg(hp + (k0 + U + uu) * (Bsz / 2));
        }
#pragma unroll
        for (int uu = 0; uu < U; uu++) {
            ull hA = pack2(hbuf[uu].x, hbuf[uu].x);
            ull hB = pack2(hbuf[uu].y, hbuf[uu].y);
#pragma unroll
            for (int q = 0; q < NQ; q++) {
                ulonglong2 wv = *(const ulonglong2*)(wr + 4 * q);  // LDS.128 bcast
                ffma2(accA[2 * q],     wv.x, hA);
                ffma2(accB[2 * q],     wv.x, hB);
                ffma2(accA[2 * q + 1], wv.y, hA);
                ffma2(accB[2 * q + 1], wv.y, hB);
            }
            if (REM) {
                ull wv = *(const ull*)(wr + 4 * NQ);
                ffma2(accA[NCP - 1], wv, hA);
                ffma2(accB[NCP - 1], wv, hB);
            }
            wr += RS;
        }
#pragma unroll
        for (int uu = 0; uu < U; uu++) hbuf[uu] = hn[uu];
    }
}

// ---- shared epilogue: merge K-half partials in gbuf, cell update -----------
template <int NH, bool L1>
__device__ __forceinline__ void epilogue(ull* accA, ull* accB,
                                         float* __restrict__ gbuf,
                                         const float* __restrict__ wlinv,
                                         float* __restrict__ hout,
                                         float* __restrict__ out, int t,
                                         float* cst, int u0,
                                         int half, int kh, int l) {
    constexpr int NC = 4 * NH, NCH = 2 * NH, NCP = NH;
    const int b0 = 2 * l;
    float* gA = gbuf + b0 * NC + half * NCH;
    float* gB = gbuf + (b0 + 1) * NC + half * NCH;
    if (kh == 0) {
#pragma unroll
        for (int p = 0; p < NCP; p++) { ((ull*)gA)[p] = accA[p]; ((ull*)gB)[p] = accB[p]; }
    }
    __syncthreads();
    if (kh == 1) {
#pragma unroll
        for (int p = 0; p < NCP; p++) {
            float2 va = unpack2(accA[p]), vb = unpack2(accB[p]);
            gA[2 * p]     += va.x;  gA[2 * p + 1] += va.y;
            gB[2 * p]     += vb.x;  gB[2 * p + 1] += vb.y;
        }
    }
    __syncthreads();
    // cell update: 4 groups split the NH units
    constexpr int NU4 = (NH + 3) / 4;
    const int gid  = 2 * kh + half;
    const int u_lo = (NH * gid) / 4, u_hi = (NH * (gid + 1)) / 4;
    const float* g0 = gbuf + b0 * NC;
    const float* g1 = gbuf + (b0 + 1) * NC;
    float sA = 0.0f, sB = 0.0f;
#pragma unroll
    for (int jj = 0; jj < NU4; jj++) {
        int j = u_lo + jj;
        if (j < u_hi) {
            float iA = sigf(g0[j]),           iB = sigf(g1[j]);
            float fA = sigf(g0[NH + j]),      fB = sigf(g1[NH + j]);
            float gg = tanhf(g0[2 * NH + j]), gh = tanhf(g1[2 * NH + j]);
            float oA = sigf(g0[3 * NH + j]),  oB = sigf(g1[3 * NH + j]);
            float cA = fA * cst[2 * jj]     + iA * gg;
            float cB = fB * cst[2 * jj + 1] + iB * gh;
            cst[2 * jj] = cA; cst[2 * jj + 1] = cB;
            float hA_ = oA * tanhf(cA), hB_ = oB * tanhf(cB);
            if (L1) { sA += wlinv[j] * hA_; sB += wlinv[j] * hB_; }
            __stcg((float2*)&hout[(u0 + j) * Bsz + b0], make_float2(hA_, hB_));
        }
    }
    if (L1 && u_hi > u_lo) {
        atomicAdd(out + b0 * TT + t, sA);
        atomicAdd(out + (b0 + 1) * TT + t, sB);
    }
}

// ---------------- layer 0 step ----------------------------------------------
template <int NH>
__device__ __forceinline__ void l0_step(const float* __restrict__ ws,
                                        const float* __restrict__ biasv,
                                        const float* __restrict__ wihv,
                                        float* __restrict__ gbuf,
                                        const float* __restrict__ hprev,
                                        float* __restrict__ hout,
                                        float2 xv, float* cst,
                                        int u0, int half, int kh, int l) {
    constexpr int NCH = 2 * NH, GP = (NCH + 3) & ~3, RS = 2 * GP, NCP = NH;
    constexpr int KH = Hd / 2;
    const int b0 = 2 * l;
    ull accA[NCP], accB[NCP];
    if (kh == 0) {
        const ull* bh  = (const ull*)(biasv + half * NCH);
        const ull* wih = (const ull*)(wihv + half * NCH);
        ull xA = pack2(xv.x, xv.x), xB = pack2(xv.y, xv.y);
#pragma unroll
        for (int p = 0; p < NCP; p++) {
            ull b = bh[p]; accA[p] = b; accB[p] = b;
            ull w = wih[p];
            ffma2(accA[p], w, xA);
            ffma2(accB[p], w, xB);
        }
    } else {
        ull z = pack2(0.0f, 0.0f);
#pragma unroll
        for (int p = 0; p < NCP; p++) { accA[p] = z; accB[p] = z; }
    }
    dotloop<NCH, RS, KH>(accA, accB, ws + kh * KH * RS + half * GP,
                         (const float2*)(hprev + kh * KH * Bsz + b0));
    epilogue<NH, false>(accA, accB, gbuf, (const float*)0, hout,
                        (float*)0, 0, cst, u0, half, kh, l);
}

// ---------------- layer 1 step ----------------------------------------------
template <int NH>
__device__ __forceinline__ void l1_step(const float* __restrict__ ws,
                                        const float* __restrict__ biasv,
                                        const float* __restrict__ wlinv,
                                        float* __restrict__ gbuf,
                                        const float* __restrict__ h0cur,
                                        const float* __restrict__ h1prev,
                                        float* __restrict__ hout,
                                        float* __restrict__ out, int t,
                                        float* cst, int u0, int half, int kh, int l) {
    constexpr int NCH = 2 * NH, GP = (NCH + 3) & ~3, RS = 2 * GP, NCP = NH;
    const int b0 = 2 * l;
    ull accA[NCP], accB[NCP];
    if (kh == 0) {
        const ull* bh = (const ull*)(biasv + half * NCH);
#pragma unroll
        for (int p = 0; p < NCP; p++) { accA[p] = bh[p]; accB[p] = bh[p]; }
    } else {
        ull z = pack2(0.0f, 0.0f);
#pragma unroll
        for (int p = 0; p < NCP; p++) { accA[p] = z; accB[p] = z; }
    }
    const float*  hsrc = (kh == 0) ? h0cur : h1prev;
    dotloop<NCH, RS, Hd>(accA, accB, ws + kh * Hd * RS + half * GP,
                         (const float2*)(hsrc + b0));
    epilogue<NH, true>(accA, accB, gbuf, wlinv, hout, out, t, cst, u0, half, kh, l);
}

// ---------------- per-CTA loops (barrier sequences identical) ---------------
template <int NH>
__device__ __noinline__ void run_l0(const float* ws, const float* biasv, const float* wihv,
                                    float* gbuf, float* out, int u0, unsigned gen0,
                                    int half, int kh, int l) {
    constexpr int NU4 = (NH + 3) / 4;
    float cst[2 * NU4];
#pragma unroll
    for (int j = 0; j < 2 * NU4; j++) cst[j] = 0.0f;
    const int b0 = 2 * l;
    unsigned nbar = 2;
    for (int s = 0; s <= Tm; s++) {
        if (s < Tm) {
            float2 xv = *(const float2*)&g_xT[s * Bsz + b0];
            l0_step<NH>(ws, biasv, wihv, gbuf,
                        g_h0 + ((unsigned)(s + 1) & 1u) * HB,
                        g_h0 + ((unsigned)s & 1u) * HB,
                        xv, cst, u0, half, kh, l);
        }
        gsync(gen0 + nbar); nbar++;
    }
    for (int f = 0; f < FUTN; f++) {
        int t = Tm + f;
        float2 xv;
        xv.x = __ldcg(&out[b0 * TT + (t - 1)]);
        xv.y = __ldcg(&out[(b0 + 1) * TT + (t - 1)]);
        l0_step<NH>(ws, biasv, wihv, gbuf,
                    g_h0 + ((unsigned)(t + 1) & 1u) * HB,
                    g_h0 + ((unsigned)t & 1u) * HB,
                    xv, cst, u0, half, kh, l);
        gsync(gen0 + nbar); nbar++;
        gsync(gen0 + nbar); nbar++;
    }
}

template <int NH>
__device__ __noinline__ void run_l1(const float* ws, const float* biasv, const float* wlinv,
                                    float* gbuf, float* out, int u0, unsigned gen0,
                                    int half, int kh, int l) {
    constexpr int NU4 = (NH + 3) / 4;
    float cst[2 * NU4];
#pragma unroll
    for (int j = 0; j < 2 * NU4; j++) cst[j] = 0.0f;
    unsigned nbar = 2;
    for (int s = 0; s <= Tm; s++) {
        if (s >= 1) {
            int t = s - 1;
            l1_step<NH>(ws, biasv, wlinv, gbuf,
                        g_h0 + ((unsigned)t & 1u) * HB,
                        g_h1 + ((unsigned)(t + 1) & 1u) * HB,
                        g_h1 + ((unsigned)t & 1u) * HB,
                        out, t, cst, u0, half, kh, l);
        }
        gsync(gen0 + nbar); nbar++;
    }
    for (int f = 0; f < FUTN; f++) {
        int t = Tm + f;
        gsync(gen0 + nbar); nbar++;
        l1_step<NH>(ws, biasv, wlinv, gbuf,
                    g_h0 + ((unsigned)t & 1u) * HB,
                    g_h1 + ((unsigned)(t + 1) & 1u) * HB,
                    g_h1 + ((unsigned)t & 1u) * HB,
                    out, t, cst, u0, half, kh, l);
        gsync(gen0 + nbar); nbar++;
    }
}

// ---------------------------------------------------------------------------
__global__ void __launch_bounds__(NTHR, 1)
lstm_persistent_kernel(const float* __restrict__ x,
                       const float* __restrict__ Wih0, const float* __restrict__ Whh0,
                       const float* __restrict__ bih0, const float* __restrict__ bhh0,
                       const float* __restrict__ Wih1, const float* __restrict__ Whh1,
                       const float* __restrict__ bih1, const float* __restrict__ bhh1,
                       const float* __restrict__ Wlin, const float* __restrict__ blin,
                       float* __restrict__ out) {
    extern __shared__ float smem[];
    const int tid  = threadIdx.x;
    const int bid  = blockIdx.x;
    const int l    = tid & 127;          // batch pair
    const int half = (tid >> 7) & 1;     // column half
    const int kh   = tid >> 8;           // K half

    __shared__ unsigned s_gen0;
    if (tid == 0) s_gen0 = *((volatile unsigned*)&g_gen);
    __syncthreads();
    const unsigned gen0 = s_gen0;

    const bool isL0 = (bid < N0);
    const int  gi   = isL0 ? bid : bid - N0;
    int u0, u1;
    if (isL0) { u0 = (Hd * gi) / N0; u1 = (Hd * (gi + 1)) / N0; }
    else      { u0 = (Hd * gi) / N1; u1 = (Hd * (gi + 1)) / N1; }
    const int nh  = u1 - u0;
    const int nc  = 4 * nh;
    const int nch = 2 * nh;
    const int gp  = (nch + 3) & ~3;
    const int rs  = 2 * gp;
    const int K   = isL0 ? Hd : 2 * Hd;

    float* ws    = smem;            // [K][rs] padded, col-half h at offset h*gp
    float* biasv = smem + K * rs;   // [nc] gate-major (bih+bhh)
    float* auxv  = biasv + nc;      // layer0: Wih0 col [nc]; layer1: Wlin [nh]
    float* gbuf  = auxv + nc;       // [Bsz][nc] gate exchange

    // ---- one-time weight staging ------------------------------------------
    if (isL0) {
        for (int c = 0; c < nc; c++) {
            int g = c / nch, lc = c - g * nch;
            int gate = c / nh, j = c - gate * nh;
            int row = gate * Hd + u0 + j;
            int dc = g * gp + lc;
            for (int k = tid; k < Hd; k += NTHR) ws[k * rs + dc] = Whh0[row * Hd + k];
            if (tid == 0) { biasv[c] = bih0[row] + bhh0[row]; auxv[c] = Wih0[row]; }
        }
    } else {
        for (int c = 0; c < nc; c++) {
            int g = c / nch, lc = c - g * nch;
            int gate = c / nh, j = c - gate * nh;
            int row = gate * Hd + u0 + j;
            int dc = g * gp + lc;
            for (int k = tid; k < Hd; k += NTHR) {
                ws[k * rs + dc]        = Wih1[row * Hd + k];
                ws[(Hd + k) * rs + dc] = Whh1[row * Hd + k];
            }
            if (tid == 0) biasv[c] = bih1[row] + bhh1[row];
        }
        if (tid == 0) for (int j = 0; j < nh; j++) auxv[j] = Wlin[u0 + j];
    }

    // ---- per-launch global init (idempotent across graph replays) ---------
    const float bl = blin[0];
    for (int i = bid * NTHR + tid; i < Bsz * TT; i += NBLK * NTHR) __stcg(&out[i], bl);
    for (int i = bid * NTHR + tid; i < 2 * HB; i += NBLK * NTHR) {
        __stcg(&g_h0[i], 0.0f);
        __stcg(&g_h1[i], 0.0f);
    }
    for (int i = bid * NTHR + tid; i < Bsz * Tm; i += NBLK * NTHR) {
        int b = i / Tm, t = i - b * Tm;
        __stcg(&g_xT[t * Bsz + b], x[i]);
    }
    gsync(gen0 + 1);

    if (isL0) {
        if (nh == 11) run_l0<11>(ws, biasv, auxv, gbuf, out, u0, gen0, half, kh, l);
        else          run_l0<10>(ws, biasv, auxv, gbuf, out, u0, gen0, half, kh, l);
    } else {
        if (nh == 6)  run_l1<6 >(ws, biasv, auxv, gbuf, out, u0, gen0, half, kh, l);
        else          run_l1<5 >(ws, biasv, auxv, gbuf, out, u0, gen0, half, kh, l);
    }
}

// ---------------------------------------------------------------------------
extern "C" void kernel_launch(void* const* d_in, const int* in_sizes, int n_in,
                              void* d_out, int out_size) {
    (void)in_sizes; (void)n_in; (void)out_size;
    const float* x    = (const float*)d_in[0];
    const float* Wih0 = (const float*)d_in[1];
    const float* Whh0 = (const float*)d_in[2];
    const float* bih0 = (const float*)d_in[3];
    const float* bhh0 = (const float*)d_in[4];
    const float* Wih1 = (const float*)d_in[5];
    const float* Whh1 = (const float*)d_in[6];
    const float* bih1 = (const float*)d_in[7];
    const float* bhh1 = (const float*)d_in[8];
    const float* Wlin = (const float*)d_in[9];
    const float* blin = (const float*)d_in[10];
    float* out = (float*)d_out;

    cudaFuncSetAttribute(lstm_persistent_kernel,
                         cudaFuncAttributeMaxDynamicSharedMemorySize, SMEM_BYTES);

    lstm_persistent_kernel<<<NBLK, NTHR, SMEM_BYTES>>>(
        x, Wih0, Whh0, bih0, bhh0, Wih1, Whh1, bih1, bhh1, Wlin, blin, out);
}